// round 15
// baseline (speedup 1.0000x reference)
#include <cuda_runtime.h>
#include <cuda_fp16.h>

#define N_NODES 100000
#define N_EDGES 1600000
#define N_DIR   (2 * N_EDGES)
#define DIM     64
#define NB_SCAN 98            // ceil(100000 / 1024)

// -------- scratch (device globals; no allocation allowed) --------
__device__ int    g_cnt[N_NODES];
__device__ int    g_off[N_NODES + 1];
__device__ int    g_cur[N_NODES];
__device__ float  g_dis[N_NODES];              // deg^-1/2 (0 if deg==0)
__device__ float  g_sq[N_NODES];               // deg^+1/2 (0 if deg==0)
__device__ int    g_src[N_DIR];
__device__ int    g_bsum[NB_SCAN];
__device__ __half g_zA[N_NODES * DIM];         // z0
__device__ __half g_zB[N_NODES * DIM];         // z1
__device__ __half g_zC[N_NODES * DIM];         // z2

// -------- 1. zero degree counters (vectorized) --------
__global__ void k_zero_cnt() {
    int i4 = blockIdx.x * blockDim.x + threadIdx.x;
    if (i4 < N_NODES / 4)
        reinterpret_cast<int4*>(g_cnt)[i4] = make_int4(0, 0, 0, 0);
}

// -------- 2. degree count: 8 undirected edges per thread --------
__global__ void k_count(const int* __restrict__ adj) {
    int t = blockIdx.x * blockDim.x + threadIdx.x;
    int e8 = t * 8;
    if (e8 >= N_EDGES) return;
    int4 r0 = *reinterpret_cast<const int4*>(adj + e8);
    int4 r1 = *reinterpret_cast<const int4*>(adj + e8 + 4);
    int4 c0 = *reinterpret_cast<const int4*>(adj + N_EDGES + e8);
    int4 c1 = *reinterpret_cast<const int4*>(adj + N_EDGES + e8 + 4);
    atomicAdd(&g_cnt[r0.x], 1); atomicAdd(&g_cnt[c0.x], 1);
    atomicAdd(&g_cnt[r0.y], 1); atomicAdd(&g_cnt[c0.y], 1);
    atomicAdd(&g_cnt[r0.z], 1); atomicAdd(&g_cnt[c0.z], 1);
    atomicAdd(&g_cnt[r0.w], 1); atomicAdd(&g_cnt[c0.w], 1);
    atomicAdd(&g_cnt[r1.x], 1); atomicAdd(&g_cnt[c1.x], 1);
    atomicAdd(&g_cnt[r1.y], 1); atomicAdd(&g_cnt[c1.y], 1);
    atomicAdd(&g_cnt[r1.z], 1); atomicAdd(&g_cnt[c1.z], 1);
    atomicAdd(&g_cnt[r1.w], 1); atomicAdd(&g_cnt[c1.w], 1);
}

// -------- 3a. per-block sums of g_cnt (1024 nodes / block) --------
__global__ void k_scan1() {
    int b = blockIdx.x, t = threadIdx.x;
    int lane = t & 31, wid = t >> 5;
    int i4 = b * 256 + t;
    int4 v = (i4 * 4 < N_NODES) ? reinterpret_cast<const int4*>(g_cnt)[i4]
                                : make_int4(0, 0, 0, 0);
    int s = v.x + v.y + v.z + v.w;
    #pragma unroll
    for (int o = 16; o > 0; o >>= 1) s += __shfl_down_sync(0xffffffffu, s, o);
    __shared__ int ws[8];
    if (lane == 0) ws[wid] = s;
    __syncthreads();
    if (wid == 0) {
        int x = (lane < 8) ? ws[lane] : 0;
        #pragma unroll
        for (int o = 4; o > 0; o >>= 1) x += __shfl_down_sync(0xffffffffu, x, o);
        if (lane == 0) g_bsum[b] = x;
    }
}

// -------- 3b. fused: block base (reduction over bsum[0..b-1]) + local scan
//            + emit g_off/g_cur/g_dis/g_sq + z0 init --------
__global__ void __launch_bounds__(256)
k_scan3(const float* __restrict__ x) {
    __shared__ int   wr[8];
    __shared__ int   ws[8];
    __shared__ int   s_base;
    __shared__ float s_dis[1024];
    int b = blockIdx.x, t = threadIdx.x;
    int lane = t & 31, wid = t >> 5;

    // base = sum_{j<b} g_bsum[j]  (masked block reduction; b <= 97 < 256)
    int r = (t < b) ? g_bsum[t] : 0;
    #pragma unroll
    for (int o = 16; o > 0; o >>= 1) r += __shfl_down_sync(0xffffffffu, r, o);
    if (lane == 0) wr[wid] = r;
    __syncthreads();
    if (t == 0) {
        int s = 0;
        #pragma unroll
        for (int j = 0; j < 8; j++) s += wr[j];
        s_base = s;
    }
    __syncthreads();

    // local scan over this block's 1024 counts
    int i4 = b * 256 + t;
    bool ok = (i4 * 4 < N_NODES);
    int4 v = ok ? reinterpret_cast<const int4*>(g_cnt)[i4] : make_int4(0, 0, 0, 0);
    int tsum = v.x + v.y + v.z + v.w;
    int incl = tsum;
    #pragma unroll
    for (int o = 1; o < 32; o <<= 1) {
        int u = __shfl_up_sync(0xffffffffu, incl, o);
        if (lane >= o) incl += u;
    }
    if (lane == 31) ws[wid] = incl;
    __syncthreads();
    if (wid == 0 && lane < 8) {
        int s = ws[lane];
        #pragma unroll
        for (int o = 1; o < 8; o <<= 1) {
            int u = __shfl_up_sync(0x000000ffu, s, o);
            if (lane >= o) s += u;
        }
        ws[lane] = s;
    }
    __syncthreads();
    int base = s_base + (incl - tsum) + ((wid > 0) ? ws[wid - 1] : 0);
    if (ok) {
        int o0 = base, o1 = o0 + v.x, o2 = o1 + v.y, o3 = o2 + v.z;
        int4 off = make_int4(o0, o1, o2, o3);
        reinterpret_cast<int4*>(g_off)[i4] = off;
        reinterpret_cast<int4*>(g_cur)[i4] = off;
        float4 dd, qq;
        dd.x = (v.x > 0) ? rsqrtf((float)v.x) : 0.0f;
        dd.y = (v.y > 0) ? rsqrtf((float)v.y) : 0.0f;
        dd.z = (v.z > 0) ? rsqrtf((float)v.z) : 0.0f;
        dd.w = (v.w > 0) ? rsqrtf((float)v.w) : 0.0f;
        qq.x = (v.x > 0) ? sqrtf((float)v.x) : 0.0f;
        qq.y = (v.y > 0) ? sqrtf((float)v.y) : 0.0f;
        qq.z = (v.z > 0) ? sqrtf((float)v.z) : 0.0f;
        qq.w = (v.w > 0) ? sqrtf((float)v.w) : 0.0f;
        reinterpret_cast<float4*>(g_dis)[i4] = dd;
        reinterpret_cast<float4*>(g_sq)[i4]  = qq;
        s_dis[t * 4 + 0] = dd.x;
        s_dis[t * 4 + 1] = dd.y;
        s_dis[t * 4 + 2] = dd.z;
        s_dis[t * 4 + 3] = dd.w;
    }
    if (b == 0 && t == 0) g_off[N_NODES] = N_DIR;
    __syncthreads();

    // z0 init for this block's 1024 nodes: z0 = half(dis .* x)
    const float2* x2 = reinterpret_cast<const float2*>(x);
    __half2* z = reinterpret_cast<__half2*>(g_zA);
    int ebase = b * 1024 * 32;                 // half2 elements
    for (int e = t; e < 1024 * 32; e += 256) {
        int g = ebase + e;
        if (g >= N_NODES * 32) break;
        float2 vx = __ldg(&x2[g]);
        float  d  = s_dis[e >> 5];
        z[g] = __floats2half2_rn(vx.x * d, vx.y * d);
    }
}

// -------- 4. place directed edges into CSR-by-dest (index only) --------
__global__ void k_place(const int* __restrict__ adj) {
    int t = blockIdx.x * blockDim.x + threadIdx.x;
    int e8 = t * 8;
    if (e8 >= N_EDGES) return;
    int4 r0 = *reinterpret_cast<const int4*>(adj + e8);
    int4 r1 = *reinterpret_cast<const int4*>(adj + e8 + 4);
    int4 c0 = *reinterpret_cast<const int4*>(adj + N_EDGES + e8);
    int4 c1 = *reinterpret_cast<const int4*>(adj + N_EDGES + e8 + 4);
    int p0  = atomicAdd(&g_cur[c0.x], 1);
    int p1  = atomicAdd(&g_cur[r0.x], 1);
    int p2  = atomicAdd(&g_cur[c0.y], 1);
    int p3  = atomicAdd(&g_cur[r0.y], 1);
    int p4  = atomicAdd(&g_cur[c0.z], 1);
    int p5  = atomicAdd(&g_cur[r0.z], 1);
    int p6  = atomicAdd(&g_cur[c0.w], 1);
    int p7  = atomicAdd(&g_cur[r0.w], 1);
    int p8  = atomicAdd(&g_cur[c1.x], 1);
    int p9  = atomicAdd(&g_cur[r1.x], 1);
    int p10 = atomicAdd(&g_cur[c1.y], 1);
    int p11 = atomicAdd(&g_cur[r1.y], 1);
    int p12 = atomicAdd(&g_cur[c1.z], 1);
    int p13 = atomicAdd(&g_cur[r1.z], 1);
    int p14 = atomicAdd(&g_cur[c1.w], 1);
    int p15 = atomicAdd(&g_cur[r1.w], 1);
    g_src[p0]  = r0.x;  g_src[p1]  = c0.x;
    g_src[p2]  = r0.y;  g_src[p3]  = c0.y;
    g_src[p4]  = r0.z;  g_src[p5]  = c0.z;
    g_src[p6]  = r0.w;  g_src[p7]  = c0.w;
    g_src[p8]  = r1.x;  g_src[p9]  = c1.x;
    g_src[p10] = r1.y;  g_src[p11] = c1.y;
    g_src[p12] = r1.z;  g_src[p13] = c1.z;
    g_src[p14] = r1.w;  g_src[p15] = c1.w;
}

// -------- 5. SpMM layers: one warp per destination node --------
// Edges processed in groups of 4: three HADD2 then one convert (4.75 instr/edge).
// NONFINAL: z_out = half(dis^2 * sum_{nb} z_in[src]).
// FINAL:    out = 0.25*(x + sq*(z1+z2) + dis*sum_{nb} z_in[src]).
template <bool FINAL>
__global__ void __launch_bounds__(256)
k_spmm(const __half2* __restrict__ zin, __half2* __restrict__ zout,
       const float* __restrict__ x, const __half2* __restrict__ z1,
       float* __restrict__ out) {
    int warp_g = (blockIdx.x * blockDim.x + threadIdx.x) >> 5;
    int lane   = threadIdx.x & 31;
    if (warp_g >= N_NODES) return;
    int n   = warp_g;
    int beg = __ldg(&g_off[n]);
    int end = __ldg(&g_off[n + 1]);

    float2 acc = make_float2(0.0f, 0.0f);
    const __half2* zl = zin + lane;

    int base = beg;
    for (; base + 32 <= end; base += 32) {
        int s = __ldg(&g_src[base + lane]);
        #pragma unroll
        for (int k = 0; k < 32; k += 4) {
            int s0 = __shfl_sync(0xffffffffu, s, k);
            int s1 = __shfl_sync(0xffffffffu, s, k + 1);
            int s2 = __shfl_sync(0xffffffffu, s, k + 2);
            int s3 = __shfl_sync(0xffffffffu, s, k + 3);
            __half2 a = __ldg(zl + s0 * 32);
            __half2 b = __ldg(zl + s1 * 32);
            __half2 c = __ldg(zl + s2 * 32);
            __half2 e = __ldg(zl + s3 * 32);
            __half2 ab = __hadd2(a, b);
            __half2 ce = __hadd2(c, e);
            float2 v = __half22float2(__hadd2(ab, ce));
            acc.x += v.x;
            acc.y += v.y;
        }
    }
    int rem = end - base;
    if (rem > 0) {
        int s = (lane < rem) ? __ldg(&g_src[base + lane]) : 0;
        int k = 0;
        for (; k + 4 <= rem; k += 4) {
            int s0 = __shfl_sync(0xffffffffu, s, k);
            int s1 = __shfl_sync(0xffffffffu, s, k + 1);
            int s2 = __shfl_sync(0xffffffffu, s, k + 2);
            int s3 = __shfl_sync(0xffffffffu, s, k + 3);
            __half2 a = __ldg(zl + s0 * 32);
            __half2 b = __ldg(zl + s1 * 32);
            __half2 c = __ldg(zl + s2 * 32);
            __half2 e = __ldg(zl + s3 * 32);
            __half2 ab = __hadd2(a, b);
            __half2 ce = __hadd2(c, e);
            float2 v = __half22float2(__hadd2(ab, ce));
            acc.x += v.x;
            acc.y += v.y;
        }
        for (; k < rem; k++) {
            int s0 = __shfl_sync(0xffffffffu, s, k);
            float2 v = __half22float2(__ldg(zl + s0 * 32));
            acc.x += v.x;
            acc.y += v.y;
        }
    }

    float d = __ldg(&g_dis[n]);
    int o = n * 32 + lane;                     // float2 / half2 index
    if (FINAL) {
        float  sq = __ldg(&g_sq[n]);
        float2 xv = __ldg(reinterpret_cast<const float2*>(x) + o);
        float2 a1 = __half22float2(__ldg(z1 + o));
        float2 a2 = __half22float2(__ldg(zin + o));   // z2 == gather source
        float2 r;
        r.x = 0.25f * (xv.x + sq * (a1.x + a2.x) + d * acc.x);
        r.y = 0.25f * (xv.y + sq * (a1.y + a2.y) + d * acc.y);
        reinterpret_cast<float2*>(out)[o] = r;
    } else {
        float d2 = d * d;
        zout[o] = __floats2half2_rn(d2 * acc.x, d2 * acc.y);
    }
}

extern "C" void kernel_launch(void* const* d_in, const int* in_sizes, int n_in,
                              void* d_out, int out_size) {
    (void)in_sizes; (void)n_in; (void)out_size;
    const float* x   = (const float*)d_in[0];
    const int*   adj = (const int*)d_in[1];
    float*       out = (float*)d_out;

    void *pA = nullptr, *pB = nullptr, *pC = nullptr;
    cudaGetSymbolAddress(&pA, g_zA);
    cudaGetSymbolAddress(&pB, g_zB);
    cudaGetSymbolAddress(&pC, g_zC);
    __half2* zA = (__half2*)pA;   // z0
    __half2* zB = (__half2*)pB;   // z1
    __half2* zC = (__half2*)pC;   // z2

    const int T = 256;
    k_zero_cnt<<<(N_NODES / 4 + T - 1) / T, T>>>();
    k_count<<<(N_EDGES / 8 + T - 1) / T, T>>>(adj);
    k_scan1<<<NB_SCAN, 256>>>();
    k_scan3<<<NB_SCAN, 256>>>(x);
    k_place<<<(N_EDGES / 8 + T - 1) / T, T>>>(adj);

    int spmm_blocks = (N_NODES * 32 + T - 1) / T;  // one warp per node
    k_spmm<false><<<spmm_blocks, T>>>(zA, zB, nullptr, nullptr, nullptr); // z1
    k_spmm<false><<<spmm_blocks, T>>>(zB, zC, nullptr, nullptr, nullptr); // z2
    k_spmm<true ><<<spmm_blocks, T>>>(zC, nullptr, x, zB, out);           // out
}

// round 17
// speedup vs baseline: 1.2432x; 1.2432x over previous
#include <cuda_runtime.h>
#include <cuda_fp16.h>

#define N_NODES 100000
#define N_EDGES 1600000
#define N_DIR   (2 * N_EDGES)
#define DIM     64
#define NB_SCAN 98            // ceil(100000 / 1024)

// -------- scratch (device globals; no allocation allowed) --------
__device__ int    g_cnt[N_NODES];
__device__ int    g_off[N_NODES + 1];
__device__ int    g_cur[N_NODES];
__device__ float  g_dis[N_NODES];              // deg^-1/2 (0 if deg==0)
__device__ float  g_sq[N_NODES];               // deg^+1/2 (0 if deg==0)
__device__ int    g_src[N_DIR];
__device__ int    g_bsum[NB_SCAN];
__device__ __half g_zA[N_NODES * DIM];         // z0
__device__ __half g_zB[N_NODES * DIM];         // z1
__device__ __half g_zC[N_NODES * DIM];         // z2

// -------- 1. zero degree counters (vectorized) --------
__global__ void k_zero_cnt() {
    int i4 = blockIdx.x * blockDim.x + threadIdx.x;
    if (i4 < N_NODES / 4)
        reinterpret_cast<int4*>(g_cnt)[i4] = make_int4(0, 0, 0, 0);
}

// -------- 2. degree count: 8 undirected edges per thread --------
__global__ void k_count(const int* __restrict__ adj) {
    int t = blockIdx.x * blockDim.x + threadIdx.x;
    int e8 = t * 8;
    if (e8 >= N_EDGES) return;
    int4 r0 = *reinterpret_cast<const int4*>(adj + e8);
    int4 r1 = *reinterpret_cast<const int4*>(adj + e8 + 4);
    int4 c0 = *reinterpret_cast<const int4*>(adj + N_EDGES + e8);
    int4 c1 = *reinterpret_cast<const int4*>(adj + N_EDGES + e8 + 4);
    atomicAdd(&g_cnt[r0.x], 1); atomicAdd(&g_cnt[c0.x], 1);
    atomicAdd(&g_cnt[r0.y], 1); atomicAdd(&g_cnt[c0.y], 1);
    atomicAdd(&g_cnt[r0.z], 1); atomicAdd(&g_cnt[c0.z], 1);
    atomicAdd(&g_cnt[r0.w], 1); atomicAdd(&g_cnt[c0.w], 1);
    atomicAdd(&g_cnt[r1.x], 1); atomicAdd(&g_cnt[c1.x], 1);
    atomicAdd(&g_cnt[r1.y], 1); atomicAdd(&g_cnt[c1.y], 1);
    atomicAdd(&g_cnt[r1.z], 1); atomicAdd(&g_cnt[c1.z], 1);
    atomicAdd(&g_cnt[r1.w], 1); atomicAdd(&g_cnt[c1.w], 1);
}

// -------- 3a. per-block sums of g_cnt (1024 nodes / block) --------
__global__ void k_scan1() {
    int b = blockIdx.x, t = threadIdx.x;
    int lane = t & 31, wid = t >> 5;
    int i4 = b * 256 + t;
    int4 v = (i4 * 4 < N_NODES) ? reinterpret_cast<const int4*>(g_cnt)[i4]
                                : make_int4(0, 0, 0, 0);
    int s = v.x + v.y + v.z + v.w;
    #pragma unroll
    for (int o = 16; o > 0; o >>= 1) s += __shfl_down_sync(0xffffffffu, s, o);
    __shared__ int ws[8];
    if (lane == 0) ws[wid] = s;
    __syncthreads();
    if (wid == 0) {
        int x = (lane < 8) ? ws[lane] : 0;
        #pragma unroll
        for (int o = 4; o > 0; o >>= 1) x += __shfl_down_sync(0xffffffffu, x, o);
        if (lane == 0) g_bsum[b] = x;
    }
}

// -------- 3b. fused: block base (reduction over bsum[0..b-1]) + local scan
//            + emit g_off/g_cur/g_dis/g_sq (NO z0 init — parallelism!) ------
__global__ void __launch_bounds__(256)
k_scan3() {
    __shared__ int wr[8];
    __shared__ int ws[8];
    __shared__ int s_base;
    int b = blockIdx.x, t = threadIdx.x;
    int lane = t & 31, wid = t >> 5;

    // base = sum_{j<b} g_bsum[j]  (masked block reduction; b <= 97 < 256)
    int r = (t < b) ? g_bsum[t] : 0;
    #pragma unroll
    for (int o = 16; o > 0; o >>= 1) r += __shfl_down_sync(0xffffffffu, r, o);
    if (lane == 0) wr[wid] = r;
    __syncthreads();
    if (t == 0) {
        int s = 0;
        #pragma unroll
        for (int j = 0; j < 8; j++) s += wr[j];
        s_base = s;
    }
    __syncthreads();

    // local scan over this block's 1024 counts
    int i4 = b * 256 + t;
    bool ok = (i4 * 4 < N_NODES);
    int4 v = ok ? reinterpret_cast<const int4*>(g_cnt)[i4] : make_int4(0, 0, 0, 0);
    int tsum = v.x + v.y + v.z + v.w;
    int incl = tsum;
    #pragma unroll
    for (int o = 1; o < 32; o <<= 1) {
        int u = __shfl_up_sync(0xffffffffu, incl, o);
        if (lane >= o) incl += u;
    }
    if (lane == 31) ws[wid] = incl;
    __syncthreads();
    if (wid == 0 && lane < 8) {
        int s = ws[lane];
        #pragma unroll
        for (int o = 1; o < 8; o <<= 1) {
            int u = __shfl_up_sync(0x000000ffu, s, o);
            if (lane >= o) s += u;
        }
        ws[lane] = s;
    }
    __syncthreads();
    int base = s_base + (incl - tsum) + ((wid > 0) ? ws[wid - 1] : 0);
    if (ok) {
        int o0 = base, o1 = o0 + v.x, o2 = o1 + v.y, o3 = o2 + v.z;
        int4 off = make_int4(o0, o1, o2, o3);
        reinterpret_cast<int4*>(g_off)[i4] = off;
        reinterpret_cast<int4*>(g_cur)[i4] = off;
        float4 dd, qq;
        dd.x = (v.x > 0) ? rsqrtf((float)v.x) : 0.0f;
        dd.y = (v.y > 0) ? rsqrtf((float)v.y) : 0.0f;
        dd.z = (v.z > 0) ? rsqrtf((float)v.z) : 0.0f;
        dd.w = (v.w > 0) ? rsqrtf((float)v.w) : 0.0f;
        qq.x = (v.x > 0) ? sqrtf((float)v.x) : 0.0f;
        qq.y = (v.y > 0) ? sqrtf((float)v.y) : 0.0f;
        qq.z = (v.z > 0) ? sqrtf((float)v.z) : 0.0f;
        qq.w = (v.w > 0) ? sqrtf((float)v.w) : 0.0f;
        reinterpret_cast<float4*>(g_dis)[i4] = dd;
        reinterpret_cast<float4*>(g_sq)[i4]  = qq;
    }
    if (b == 0 && t == 0) g_off[N_NODES] = N_DIR;
}

// -------- 4. place directed edges into CSR-by-dest (index only) --------
__global__ void k_place(const int* __restrict__ adj) {
    int t = blockIdx.x * blockDim.x + threadIdx.x;
    int e8 = t * 8;
    if (e8 >= N_EDGES) return;
    int4 r0 = *reinterpret_cast<const int4*>(adj + e8);
    int4 r1 = *reinterpret_cast<const int4*>(adj + e8 + 4);
    int4 c0 = *reinterpret_cast<const int4*>(adj + N_EDGES + e8);
    int4 c1 = *reinterpret_cast<const int4*>(adj + N_EDGES + e8 + 4);
    int p0  = atomicAdd(&g_cur[c0.x], 1);
    int p1  = atomicAdd(&g_cur[r0.x], 1);
    int p2  = atomicAdd(&g_cur[c0.y], 1);
    int p3  = atomicAdd(&g_cur[r0.y], 1);
    int p4  = atomicAdd(&g_cur[c0.z], 1);
    int p5  = atomicAdd(&g_cur[r0.z], 1);
    int p6  = atomicAdd(&g_cur[c0.w], 1);
    int p7  = atomicAdd(&g_cur[r0.w], 1);
    int p8  = atomicAdd(&g_cur[c1.x], 1);
    int p9  = atomicAdd(&g_cur[r1.x], 1);
    int p10 = atomicAdd(&g_cur[c1.y], 1);
    int p11 = atomicAdd(&g_cur[r1.y], 1);
    int p12 = atomicAdd(&g_cur[c1.z], 1);
    int p13 = atomicAdd(&g_cur[r1.z], 1);
    int p14 = atomicAdd(&g_cur[c1.w], 1);
    int p15 = atomicAdd(&g_cur[r1.w], 1);
    g_src[p0]  = r0.x;  g_src[p1]  = c0.x;
    g_src[p2]  = r0.y;  g_src[p3]  = c0.y;
    g_src[p4]  = r0.z;  g_src[p5]  = c0.z;
    g_src[p6]  = r0.w;  g_src[p7]  = c0.w;
    g_src[p8]  = r1.x;  g_src[p9]  = c1.x;
    g_src[p10] = r1.y;  g_src[p11] = c1.y;
    g_src[p12] = r1.z;  g_src[p13] = c1.z;
    g_src[p14] = r1.w;  g_src[p15] = c1.w;
}

// -------- 5. init: z0 = half(dis .* x)  (wide grid for parallelism) --------
__global__ void k_init(const float* __restrict__ x, __half2* __restrict__ z) {
    int i = blockIdx.x * blockDim.x + threadIdx.x;   // float2 / half2 index
    if (i >= N_NODES * DIM / 2) return;
    float2 v = __ldg(reinterpret_cast<const float2*>(x) + i);
    float  d = __ldg(&g_dis[i >> 5]);
    z[i] = __floats2half2_rn(v.x * d, v.y * d);
}

// -------- 6. SpMM layers: one warp per destination node --------
// Edges processed in groups of 4: three HADD2 then one convert (4.75 instr/edge).
// NONFINAL: z_out = half(dis^2 * sum_{nb} z_in[src]).
// FINAL:    out = 0.25*(x + sq*(z1+z2) + dis*sum_{nb} z_in[src]).
template <bool FINAL>
__global__ void __launch_bounds__(256)
k_spmm(const __half2* __restrict__ zin, __half2* __restrict__ zout,
       const float* __restrict__ x, const __half2* __restrict__ z1,
       float* __restrict__ out) {
    int warp_g = (blockIdx.x * blockDim.x + threadIdx.x) >> 5;
    int lane   = threadIdx.x & 31;
    if (warp_g >= N_NODES) return;
    int n   = warp_g;
    int beg = __ldg(&g_off[n]);
    int end = __ldg(&g_off[n + 1]);

    float2 acc = make_float2(0.0f, 0.0f);
    const __half2* zl = zin + lane;

    int base = beg;
    for (; base + 32 <= end; base += 32) {
        int s = __ldg(&g_src[base + lane]);
        #pragma unroll
        for (int k = 0; k < 32; k += 4) {
            int s0 = __shfl_sync(0xffffffffu, s, k);
            int s1 = __shfl_sync(0xffffffffu, s, k + 1);
            int s2 = __shfl_sync(0xffffffffu, s, k + 2);
            int s3 = __shfl_sync(0xffffffffu, s, k + 3);
            __half2 a = __ldg(zl + s0 * 32);
            __half2 b = __ldg(zl + s1 * 32);
            __half2 c = __ldg(zl + s2 * 32);
            __half2 e = __ldg(zl + s3 * 32);
            __half2 ab = __hadd2(a, b);
            __half2 ce = __hadd2(c, e);
            float2 v = __half22float2(__hadd2(ab, ce));
            acc.x += v.x;
            acc.y += v.y;
        }
    }
    int rem = end - base;
    if (rem > 0) {
        int s = (lane < rem) ? __ldg(&g_src[base + lane]) : 0;
        int k = 0;
        for (; k + 4 <= rem; k += 4) {
            int s0 = __shfl_sync(0xffffffffu, s, k);
            int s1 = __shfl_sync(0xffffffffu, s, k + 1);
            int s2 = __shfl_sync(0xffffffffu, s, k + 2);
            int s3 = __shfl_sync(0xffffffffu, s, k + 3);
            __half2 a = __ldg(zl + s0 * 32);
            __half2 b = __ldg(zl + s1 * 32);
            __half2 c = __ldg(zl + s2 * 32);
            __half2 e = __ldg(zl + s3 * 32);
            __half2 ab = __hadd2(a, b);
            __half2 ce = __hadd2(c, e);
            float2 v = __half22float2(__hadd2(ab, ce));
            acc.x += v.x;
            acc.y += v.y;
        }
        for (; k < rem; k++) {
            int s0 = __shfl_sync(0xffffffffu, s, k);
            float2 v = __half22float2(__ldg(zl + s0 * 32));
            acc.x += v.x;
            acc.y += v.y;
        }
    }

    float d = __ldg(&g_dis[n]);
    int o = n * 32 + lane;                     // float2 / half2 index
    if (FINAL) {
        float  sq = __ldg(&g_sq[n]);
        float2 xv = __ldg(reinterpret_cast<const float2*>(x) + o);
        float2 a1 = __half22float2(__ldg(z1 + o));
        float2 a2 = __half22float2(__ldg(zin + o));   // z2 == gather source
        float2 r;
        r.x = 0.25f * (xv.x + sq * (a1.x + a2.x) + d * acc.x);
        r.y = 0.25f * (xv.y + sq * (a1.y + a2.y) + d * acc.y);
        reinterpret_cast<float2*>(out)[o] = r;
    } else {
        float d2 = d * d;
        zout[o] = __floats2half2_rn(d2 * acc.x, d2 * acc.y);
    }
}

extern "C" void kernel_launch(void* const* d_in, const int* in_sizes, int n_in,
                              void* d_out, int out_size) {
    (void)in_sizes; (void)n_in; (void)out_size;
    const float* x   = (const float*)d_in[0];
    const int*   adj = (const int*)d_in[1];
    float*       out = (float*)d_out;

    void *pA = nullptr, *pB = nullptr, *pC = nullptr;
    cudaGetSymbolAddress(&pA, g_zA);
    cudaGetSymbolAddress(&pB, g_zB);
    cudaGetSymbolAddress(&pC, g_zC);
    __half2* zA = (__half2*)pA;   // z0
    __half2* zB = (__half2*)pB;   // z1
    __half2* zC = (__half2*)pC;   // z2

    const int T = 256;
    k_zero_cnt<<<(N_NODES / 4 + T - 1) / T, T>>>();
    k_count<<<(N_EDGES / 8 + T - 1) / T, T>>>(adj);
    k_scan1<<<NB_SCAN, 256>>>();
    k_scan3<<<NB_SCAN, 256>>>();
    k_place<<<(N_EDGES / 8 + T - 1) / T, T>>>(adj);
    k_init<<<(N_NODES * DIM / 2 + T - 1) / T, T>>>(x, zA);

    int spmm_blocks = (N_NODES * 32 + T - 1) / T;  // one warp per node
    k_spmm<false><<<spmm_blocks, T>>>(zA, zB, nullptr, nullptr, nullptr); // z1
    k_spmm<false><<<spmm_blocks, T>>>(zB, zC, nullptr, nullptr, nullptr); // z2
    k_spmm<true ><<<spmm_blocks, T>>>(zC, nullptr, x, zB, out);           // out
}